// round 1
// baseline (speedup 1.0000x reference)
#include <cuda_runtime.h>
#include <math.h>

// Problem constants
#define B_  4
#define N_  1024
#define H_  1024
#define NH_ 16
#define HS_ 64
#define M_  (B_*N_)          // 4096 total rows

// GEMM tiling
#define BM 128
#define BN 128
#define BKK 8

// Scratch (no cudaMalloc allowed): q,k,v in [B,NH,N,HS] layout; feats in [B,N,H]
__device__ float g_q[B_*NH_*N_*HS_];
__device__ float g_k[B_*NH_*N_*HS_];
__device__ float g_v[B_*NH_*N_*HS_];
__device__ float g_feats[B_*N_*H_];

// ---------------------------------------------------------------------------
// QKV projection: y = x @ W + b, scattered into [B, NH, N, HS] head layout.
// blockIdx.z selects Q / K / V.
// ---------------------------------------------------------------------------
__global__ void __launch_bounds__(256) qkv_gemm(
    const float* __restrict__ x,
    const float* __restrict__ Wq, const float* __restrict__ bq,
    const float* __restrict__ Wk, const float* __restrict__ bk,
    const float* __restrict__ Wv, const float* __restrict__ bv)
{
    __shared__ float As[BKK][BM];
    __shared__ float Bs[BKK][BN];

    const float* W; const float* bias; float* out;
    if (blockIdx.z == 0)      { W = Wq; bias = bq; out = g_q; }
    else if (blockIdx.z == 1) { W = Wk; bias = bk; out = g_k; }
    else                      { W = Wv; bias = bv; out = g_v; }

    const int m0 = blockIdx.y * BM;
    const int n0 = blockIdx.x * BN;
    const int tid = threadIdx.x;

    const int aRow = tid >> 1;           // 0..127
    const int aCol = (tid & 1) * 4;      // 0 or 4
    const int bRow = tid >> 5;           // 0..7
    const int bCol = (tid & 31) * 4;     // 0..124
    const int tRow = (tid >> 4) * 8;     // 0..120
    const int tCol = (tid & 15) * 8;     // 0..120

    float acc[8][8] = {};

    for (int k0 = 0; k0 < H_; k0 += BKK) {
        float4 a4 = *(const float4*)&x[(size_t)(m0 + aRow) * H_ + k0 + aCol];
        As[aCol + 0][aRow] = a4.x;
        As[aCol + 1][aRow] = a4.y;
        As[aCol + 2][aRow] = a4.z;
        As[aCol + 3][aRow] = a4.w;
        float4 b4 = *(const float4*)&W[(size_t)(k0 + bRow) * H_ + n0 + bCol];
        *(float4*)&Bs[bRow][bCol] = b4;
        __syncthreads();

        #pragma unroll
        for (int kk = 0; kk < BKK; kk++) {
            float ra[8], rb[8];
            #pragma unroll
            for (int i = 0; i < 8; i++) ra[i] = As[kk][tRow + i];
            #pragma unroll
            for (int j = 0; j < 8; j++) rb[j] = Bs[kk][tCol + j];
            #pragma unroll
            for (int i = 0; i < 8; i++)
                #pragma unroll
                for (int j = 0; j < 8; j++)
                    acc[i][j] = fmaf(ra[i], rb[j], acc[i][j]);
        }
        __syncthreads();
    }

    // Scatter-store into [B, NH, N, HS]
    #pragma unroll
    for (int i = 0; i < 8; i++) {
        int m = m0 + tRow + i;
        int batch = m / N_;
        int nrow  = m % N_;
        #pragma unroll
        for (int j = 0; j < 8; j++) {
            int n = n0 + tCol + j;
            int h = n >> 6;
            int d = n & 63;
            out[(((size_t)batch * NH_ + h) * N_ + nrow) * HS_ + d] = acc[i][j] + bias[n];
        }
    }
}

// ---------------------------------------------------------------------------
// Output projection: out = feats @ Wp + bp (plain row-major store)
// ---------------------------------------------------------------------------
__global__ void __launch_bounds__(256) out_gemm(
    const float* __restrict__ Wp, const float* __restrict__ bp,
    float* __restrict__ out)
{
    __shared__ float As[BKK][BM];
    __shared__ float Bs[BKK][BN];

    const float* A = g_feats;
    const int m0 = blockIdx.y * BM;
    const int n0 = blockIdx.x * BN;
    const int tid = threadIdx.x;

    const int aRow = tid >> 1;
    const int aCol = (tid & 1) * 4;
    const int bRow = tid >> 5;
    const int bCol = (tid & 31) * 4;
    const int tRow = (tid >> 4) * 8;
    const int tCol = (tid & 15) * 8;

    float acc[8][8] = {};

    for (int k0 = 0; k0 < H_; k0 += BKK) {
        float4 a4 = *(const float4*)&A[(size_t)(m0 + aRow) * H_ + k0 + aCol];
        As[aCol + 0][aRow] = a4.x;
        As[aCol + 1][aRow] = a4.y;
        As[aCol + 2][aRow] = a4.z;
        As[aCol + 3][aRow] = a4.w;
        float4 b4 = *(const float4*)&Wp[(size_t)(k0 + bRow) * H_ + n0 + bCol];
        *(float4*)&Bs[bRow][bCol] = b4;
        __syncthreads();

        #pragma unroll
        for (int kk = 0; kk < BKK; kk++) {
            float ra[8], rb[8];
            #pragma unroll
            for (int i = 0; i < 8; i++) ra[i] = As[kk][tRow + i];
            #pragma unroll
            for (int j = 0; j < 8; j++) rb[j] = Bs[kk][tCol + j];
            #pragma unroll
            for (int i = 0; i < 8; i++)
                #pragma unroll
                for (int j = 0; j < 8; j++)
                    acc[i][j] = fmaf(ra[i], rb[j], acc[i][j]);
        }
        __syncthreads();
    }

    #pragma unroll
    for (int i = 0; i < 8; i++) {
        int m = m0 + tRow + i;
        #pragma unroll
        for (int j = 0; j < 8; j++) {
            int n = n0 + tCol + j;
            out[(size_t)m * H_ + n] = acc[i][j] + bp[n];
        }
    }
}

// ---------------------------------------------------------------------------
// Fused attention: per (b,h) and 64-row Q tile, flash-style online softmax.
// scores = (q @ k^T) * SCALE + bias; attn = softmax(scores); feats = attn @ v
// Bias is streamed directly from GMEM (256 MB, read once).
// ---------------------------------------------------------------------------
__global__ void __launch_bounds__(256) attn_kernel(const float* __restrict__ bias4)
{
    extern __shared__ float smem[];
    float* sQ = smem;                 // 64 x 65
    float* sK = sQ + 64 * 65;         // 64 x 65
    float* sV = sK + 64 * 65;         // 64 x 65
    float* sS = sV + 64 * 65;         // 64 x 65
    float* sM   = sS + 64 * 65;       // 64
    float* sL   = sM + 64;            // 64
    float* sFac = sL + 64;            // 64

    const int bh  = blockIdx.y;       // b*NH + h, 0..63
    const int qt  = blockIdx.x;       // 0..15
    const int tid = threadIdx.x;

    const float* qp  = g_q + ((size_t)bh * N_ + qt * 64) * HS_;
    const float* kp0 = g_k + (size_t)bh * N_ * HS_;
    const float* vp0 = g_v + (size_t)bh * N_ * HS_;
    const float* bp  = bias4 + (size_t)bh * N_ * N_ + (size_t)qt * 64 * N_;

    // Load Q tile, pre-scaled by 1/sqrt(HS)
    for (int l = tid; l < 64 * 64; l += 256) {
        int r = l >> 6, d = l & 63;
        sQ[r * 65 + d] = qp[l] * 0.125f;
    }
    if (tid < 64) { sM[tid] = -INFINITY; sL[tid] = 0.0f; }

    const int tRow = (tid >> 4) * 4;  // 0..60
    const int tCol = (tid & 15) * 4;  // 0..60

    float o[4][4] = {};

    for (int j = 0; j < N_ / 64; j++) {
        __syncthreads();   // protect sK/sV/sS reuse from previous iteration
        for (int l = tid; l < 64 * 64; l += 256) {
            int r = l >> 6, d = l & 63;
            sK[r * 65 + d] = kp0[(size_t)j * 64 * HS_ + l];
            sV[r * 65 + d] = vp0[(size_t)j * 64 * HS_ + l];
        }
        __syncthreads();

        // S = Qs @ K^T  (each thread: 4x4 sub-tile)
        float s[4][4] = {};
        #pragma unroll 8
        for (int d = 0; d < 64; d++) {
            float rq[4], rk[4];
            #pragma unroll
            for (int i = 0; i < 4; i++) rq[i] = sQ[(tRow + i) * 65 + d];
            #pragma unroll
            for (int c = 0; c < 4; c++) rk[c] = sK[(tCol + c) * 65 + d];
            #pragma unroll
            for (int i = 0; i < 4; i++)
                #pragma unroll
                for (int c = 0; c < 4; c++)
                    s[i][c] = fmaf(rq[i], rk[c], s[i][c]);
        }
        // Add bias (streamed from GMEM), spill S to SMEM for row reductions
        #pragma unroll
        for (int i = 0; i < 4; i++) {
            #pragma unroll
            for (int c = 0; c < 4; c++) {
                float val = s[i][c] + bp[(size_t)(tRow + i) * N_ + j * 64 + tCol + c];
                sS[(tRow + i) * 65 + tCol + c] = val;
            }
        }
        __syncthreads();

        // Online softmax update: one thread per row
        if (tid < 64) {
            int r = tid;
            float mo = sM[r];
            float mx = mo;
            #pragma unroll 8
            for (int c = 0; c < 64; c++) mx = fmaxf(mx, sS[r * 65 + c]);
            float fac = __expf(mo - mx);          // 0 on first tile (mo = -inf)
            float lsum = 0.0f;
            #pragma unroll 8
            for (int c = 0; c < 64; c++) {
                float p = __expf(sS[r * 65 + c] - mx);
                sS[r * 65 + c] = p;
                lsum += p;
            }
            sL[r] = sL[r] * fac + lsum;
            sM[r] = mx;
            sFac[r] = fac;
        }
        __syncthreads();

        // Rescale accumulators, then O += P @ V
        #pragma unroll
        for (int i = 0; i < 4; i++) {
            float f = sFac[tRow + i];
            #pragma unroll
            for (int c = 0; c < 4; c++) o[i][c] *= f;
        }
        #pragma unroll 8
        for (int kk = 0; kk < 64; kk++) {
            float rp[4], rv[4];
            #pragma unroll
            for (int i = 0; i < 4; i++) rp[i] = sS[(tRow + i) * 65 + kk];
            #pragma unroll
            for (int c = 0; c < 4; c++) rv[c] = sV[kk * 65 + tCol + c];
            #pragma unroll
            for (int i = 0; i < 4; i++)
                #pragma unroll
                for (int c = 0; c < 4; c++)
                    o[i][c] = fmaf(rp[i], rv[c], o[i][c]);
        }
    }

    // Normalize and write feats in [B, N, H] layout
    const int b = bh / NH_;
    const int h = bh % NH_;
    #pragma unroll
    for (int i = 0; i < 4; i++) {
        int nrow = qt * 64 + tRow + i;
        float inv = 1.0f / sL[tRow + i];
        #pragma unroll
        for (int c = 0; c < 4; c++) {
            g_feats[((size_t)b * N_ + nrow) * H_ + h * HS_ + tCol + c] = o[i][c] * inv;
        }
    }
}

// ---------------------------------------------------------------------------
// Launch
// ---------------------------------------------------------------------------
extern "C" void kernel_launch(void* const* d_in, const int* in_sizes, int n_in,
                              void* d_out, int out_size)
{
    const float* x  = (const float*)d_in[0];
    const float* ab = (const float*)d_in[1];
    const float* Wq = (const float*)d_in[2];
    const float* bq = (const float*)d_in[3];
    const float* Wk = (const float*)d_in[4];
    const float* bk = (const float*)d_in[5];
    const float* Wv = (const float*)d_in[6];
    const float* bv = (const float*)d_in[7];
    const float* Wp = (const float*)d_in[8];
    const float* bp = (const float*)d_in[9];
    float* out = (float*)d_out;

    // 1) QKV projections (z selects Q/K/V)
    dim3 gq(H_ / BN, M_ / BM, 3);
    qkv_gemm<<<gq, 256>>>(x, Wq, bq, Wk, bk, Wv, bv);

    // 2) Fused attention (needs > 48 KB dynamic SMEM)
    size_t smem = (size_t)(4 * 64 * 65 + 3 * 64) * sizeof(float);  // ~67.3 KB
    cudaFuncSetAttribute(attn_kernel, cudaFuncAttributeMaxDynamicSharedMemorySize,
                         (int)smem);
    attn_kernel<<<dim3(N_ / 64, B_ * NH_), 256, smem>>>(ab);

    // 3) Output projection
    dim3 go(H_ / BN, M_ / BM, 1);
    out_gemm<<<go, 256>>>(Wp, bp, out);
}

// round 5
// speedup vs baseline: 2.6480x; 2.6480x over previous
#include <cuda_runtime.h>
#include <math.h>
#include <stdint.h>

// Problem constants
#define B_  4
#define N_  1024
#define H_  1024
#define NH_ 16
#define HS_ 64
#define M_  (B_*N_)          // 4096 total rows

// Scratch (no cudaMalloc allowed)
__device__ float g_q[B_*NH_*N_*HS_];
__device__ float g_k[B_*NH_*N_*HS_];
__device__ float g_v[B_*NH_*N_*HS_];
__device__ float g_feats[B_*N_*H_];

// ---------------------------------------------------------------------------
// tf32 helpers (mma.sync works at compute_100 — tcgen05 does NOT)
// ---------------------------------------------------------------------------
__device__ __forceinline__ uint32_t to_tf32(float x) {
    uint32_t u;
    asm("cvt.rna.tf32.f32 %0, %1;" : "=r"(u) : "f"(x));
    return u;
}

// D = A(16x8 row) @ B(8x8 col) + C, fp32 accum
__device__ __forceinline__ void mma_tf32(float d[4], const uint32_t a[4],
                                         const uint32_t b[2], const float c[4]) {
    asm volatile(
        "mma.sync.aligned.m16n8k8.row.col.f32.tf32.tf32.f32 "
        "{%0,%1,%2,%3}, {%4,%5,%6,%7}, {%8,%9}, {%10,%11,%12,%13};"
        : "=f"(d[0]), "=f"(d[1]), "=f"(d[2]), "=f"(d[3])
        : "r"(a[0]), "r"(a[1]), "r"(a[2]), "r"(a[3]),
          "r"(b[0]), "r"(b[1]),
          "f"(c[0]), "f"(c[1]), "f"(c[2]), "f"(c[3]));
}

// ---------------------------------------------------------------------------
// GEMM: out[M,N] = A[M,K] @ W[K,N] + bias  (M=4096, N=K=1024), tf32 mma.sync
// CTA tile 128x128, K-step 32. 8 warps = 4(m) x 2(n); warp tile 32x64.
// sA: [m][k] stride 36 words (frag LDS bank = 4*tr+tc, conflict-free)
// sB: [k][n] stride 136 words (frag LDS bank = 8*tc+tr, conflict-free)
// SCATTER=true writes [B, NH, N, HS] head layout.
// ---------------------------------------------------------------------------
#define GSA 36
#define GSB 136

template<bool SCATTER>
__global__ void __launch_bounds__(256) mm_mma(
    const float* __restrict__ A,
    const float* __restrict__ Wq, const float* __restrict__ bq, float* __restrict__ oq,
    const float* __restrict__ Wk, const float* __restrict__ bk, float* __restrict__ ok,
    const float* __restrict__ Wv, const float* __restrict__ bv, float* __restrict__ ov)
{
    __shared__ uint32_t sA[128 * GSA];   // 18432 B
    __shared__ uint32_t sB[32 * GSB];    // 17408 B

    const float* W; const float* bias; float* out;
    if (blockIdx.z == 0)      { W = Wq; bias = bq; out = oq; }
    else if (blockIdx.z == 1) { W = Wk; bias = bk; out = ok; }
    else                      { W = Wv; bias = bv; out = ov; }

    const int m0 = blockIdx.y * 128;
    const int n0 = blockIdx.x * 128;
    const int tid  = threadIdx.x;
    const int lane = tid & 31;
    const int warp = tid >> 5;
    const int wm = (warp & 3) * 32;      // warp m-offset
    const int wn = (warp >> 2) * 64;     // warp n-offset
    const int tr = lane >> 2;            // 0..7
    const int tc = lane & 3;             // 0..3

    float acc[2][8][4] = {};
    float4 ra[4], rb[4];

    // Prefetch first K-slab
    #pragma unroll
    for (int i = 0; i < 4; i++) {
        int fi = tid + 256 * i;
        ra[i] = *(const float4*)&A[(size_t)(m0 + (fi >> 3)) * H_ + ((fi & 7) << 2)];
        rb[i] = *(const float4*)&W[(size_t)(fi >> 5) * H_ + n0 + ((fi & 31) << 2)];
    }

    for (int it = 0; it < 32; it++) {
        // Commit staged slab to SMEM (cvt to tf32 bits)
        #pragma unroll
        for (int i = 0; i < 4; i++) {
            int fi = tid + 256 * i;
            uint4 ua = make_uint4(to_tf32(ra[i].x), to_tf32(ra[i].y),
                                  to_tf32(ra[i].z), to_tf32(ra[i].w));
            *(uint4*)&sA[(fi >> 3) * GSA + ((fi & 7) << 2)] = ua;
            uint4 ub = make_uint4(to_tf32(rb[i].x), to_tf32(rb[i].y),
                                  to_tf32(rb[i].z), to_tf32(rb[i].w));
            *(uint4*)&sB[(fi >> 5) * GSB + ((fi & 31) << 2)] = ub;
        }
        __syncthreads();

        // Prefetch next slab (overlaps with MMA below)
        if (it < 31) {
            int k0 = (it + 1) * 32;
            #pragma unroll
            for (int i = 0; i < 4; i++) {
                int fi = tid + 256 * i;
                ra[i] = *(const float4*)&A[(size_t)(m0 + (fi >> 3)) * H_ + k0 + ((fi & 7) << 2)];
                rb[i] = *(const float4*)&W[(size_t)(k0 + (fi >> 5)) * H_ + n0 + ((fi & 31) << 2)];
            }
        }

        #pragma unroll
        for (int ks = 0; ks < 4; ks++) {
            const int kb = ks * 8;
            uint32_t af[2][4], bf[8][2];
            #pragma unroll
            for (int mi = 0; mi < 2; mi++) {
                int r = wm + mi * 16 + tr;
                af[mi][0] = sA[r * GSA + kb + tc];
                af[mi][1] = sA[(r + 8) * GSA + kb + tc];
                af[mi][2] = sA[r * GSA + kb + tc + 4];
                af[mi][3] = sA[(r + 8) * GSA + kb + tc + 4];
            }
            #pragma unroll
            for (int ni = 0; ni < 8; ni++) {
                int c = wn + ni * 8 + tr;
                bf[ni][0] = sB[(kb + tc) * GSB + c];
                bf[ni][1] = sB[(kb + tc + 4) * GSB + c];
            }
            #pragma unroll
            for (int mi = 0; mi < 2; mi++)
                #pragma unroll
                for (int ni = 0; ni < 8; ni++)
                    mma_tf32(acc[mi][ni], af[mi], bf[ni], acc[mi][ni]);
        }
        __syncthreads();
    }

    // Epilogue: c0/c1 at (row, 2*tc), c2/c3 at (row+8, 2*tc)
    #pragma unroll
    for (int mi = 0; mi < 2; mi++) {
        int r = m0 + wm + mi * 16 + tr;
        #pragma unroll
        for (int ni = 0; ni < 8; ni++) {
            int c = n0 + wn + ni * 8 + 2 * tc;
            float2 bb = *(const float2*)&bias[c];
            float2 v0 = make_float2(acc[mi][ni][0] + bb.x, acc[mi][ni][1] + bb.y);
            float2 v1 = make_float2(acc[mi][ni][2] + bb.x, acc[mi][ni][3] + bb.y);
            if (SCATTER) {
                int b = r >> 10, nr = r & 1023;
                int h = c >> 6,  d  = c & 63;
                *(float2*)&out[(((size_t)b * NH_ + h) * N_ + nr)     * HS_ + d] = v0;
                *(float2*)&out[(((size_t)b * NH_ + h) * N_ + nr + 8) * HS_ + d] = v1;
            } else {
                *(float2*)&out[(size_t)r * H_ + c]       = v0;
                *(float2*)&out[(size_t)(r + 8) * H_ + c] = v1;
            }
        }
    }
}

// ---------------------------------------------------------------------------
// Fused flash attention with tf32 mma.sync.
// Per CTA: one (b,h), one 64-row Q tile. 256 threads = 8 warps: 2(m) x 4(n),
// warp tile 32x16 over the 64x64 S / O tiles.
// sQ/sK: [row][d] stride 68 (tf32 bits); sV: [key][d] stride 72 (tf32 bits);
// sS: [q][key] stride 68 (fp32).
// ---------------------------------------------------------------------------
#define AS 68
#define VS 72
#define ATTN_SMEM ((64*AS*3 + 64*VS + 3*64) * 4)   // 71424 B

__global__ void __launch_bounds__(256) attn_mma(const float* __restrict__ bias4)
{
    extern __shared__ char smraw[];
    uint32_t* sQ = (uint32_t*)smraw;            // 64*68 words
    uint32_t* sK = sQ + 64 * AS;
    uint32_t* sV = sK + 64 * AS;                // 64*72 words
    float*    sS = (float*)(sV + 64 * VS);      // 64*68 words
    float*    sM   = sS + 64 * AS;
    float*    sL   = sM + 64;
    float*    sFac = sL + 64;

    const int bh = blockIdx.y;   // 0..63
    const int qt = blockIdx.x;   // 0..15
    const int tid  = threadIdx.x;
    const int lane = tid & 31;
    const int warp = tid >> 5;
    const int wm = (warp & 1) * 32;   // 2 warps along m
    const int wn = (warp >> 1) * 16;  // 4 warps along n
    const int tr = lane >> 2;
    const int tc = lane & 3;

    const float* qp = g_q + ((size_t)bh * N_ + qt * 64) * HS_;
    const float* kp = g_k + (size_t)bh * N_ * HS_;
    const float* vp = g_v + (size_t)bh * N_ * HS_;
    const float* bp = bias4 + (size_t)bh * N_ * N_ + (size_t)qt * 64 * N_;

    // Load Q tile (pre-scaled by 1/sqrt(HS), tf32)
    #pragma unroll
    for (int i = 0; i < 4; i++) {
        int fi = tid + 256 * i;           // 1024 float4s
        int r = fi >> 4, dq = fi & 15;
        float4 v = *(const float4*)&qp[(size_t)r * HS_ + dq * 4];
        uint4 u = make_uint4(to_tf32(v.x * 0.125f), to_tf32(v.y * 0.125f),
                             to_tf32(v.z * 0.125f), to_tf32(v.w * 0.125f));
        *(uint4*)&sQ[r * AS + dq * 4] = u;
    }
    { int r = tid >> 2; sM[r] = -INFINITY; sL[r] = 0.0f; sFac[r] = 0.0f; }

    float o[2][2][4] = {};

    for (int j = 0; j < 16; j++) {
        __syncthreads();   // prior iteration's MMA reads of sK/sV/sS done

        // Load K, V tiles (tf32 bits)
        #pragma unroll
        for (int i = 0; i < 4; i++) {
            int fi = tid + 256 * i;
            int r = fi >> 4, dq = fi & 15;
            float4 kv = *(const float4*)&kp[(size_t)(j * 64 + r) * HS_ + dq * 4];
            *(uint4*)&sK[r * AS + dq * 4] =
                make_uint4(to_tf32(kv.x), to_tf32(kv.y), to_tf32(kv.z), to_tf32(kv.w));
            float4 vv = *(const float4*)&vp[(size_t)(j * 64 + r) * HS_ + dq * 4];
            *(uint4*)&sV[r * VS + dq * 4] =
                make_uint4(to_tf32(vv.x), to_tf32(vv.y), to_tf32(vv.z), to_tf32(vv.w));
        }
        __syncthreads();

        // S = Qs @ K^T   (64x64x64)
        float sacc[2][2][4] = {};
        #pragma unroll
        for (int ks = 0; ks < 8; ks++) {
            const int kb = ks * 8;
            uint32_t af[2][4], bf[2][2];
            #pragma unroll
            for (int mi = 0; mi < 2; mi++) {
                int r = wm + mi * 16 + tr;
                af[mi][0] = sQ[r * AS + kb + tc];
                af[mi][1] = sQ[(r + 8) * AS + kb + tc];
                af[mi][2] = sQ[r * AS + kb + tc + 4];
                af[mi][3] = sQ[(r + 8) * AS + kb + tc + 4];
            }
            #pragma unroll
            for (int ni = 0; ni < 2; ni++) {
                int c = wn + ni * 8 + tr;
                bf[ni][0] = sK[c * AS + kb + tc];
                bf[ni][1] = sK[c * AS + kb + tc + 4];
            }
            #pragma unroll
            for (int mi = 0; mi < 2; mi++)
                #pragma unroll
                for (int ni = 0; ni < 2; ni++)
                    mma_tf32(sacc[mi][ni], af[mi], bf[ni], sacc[mi][ni]);
        }

        // S + bias -> sS (fp32)
        #pragma unroll
        for (int mi = 0; mi < 2; mi++) {
            int r = wm + mi * 16 + tr;
            #pragma unroll
            for (int ni = 0; ni < 2; ni++) {
                int c = wn + ni * 8 + 2 * tc;
                float2 b0 = *(const float2*)&bp[(size_t)r * N_ + j * 64 + c];
                float2 b1 = *(const float2*)&bp[(size_t)(r + 8) * N_ + j * 64 + c];
                *(float2*)&sS[r * AS + c] =
                    make_float2(sacc[mi][ni][0] + b0.x, sacc[mi][ni][1] + b0.y);
                *(float2*)&sS[(r + 8) * AS + c] =
                    make_float2(sacc[mi][ni][2] + b1.x, sacc[mi][ni][3] + b1.y);
            }
        }
        __syncthreads();

        // Online softmax: 4 lanes per row, 16 cols each
        {
            int r = tid >> 2, seg = tid & 3;
            float* row = &sS[r * AS + seg * 16];
            float4 x0 = ((float4*)row)[0], x1 = ((float4*)row)[1];
            float4 x2 = ((float4*)row)[2], x3 = ((float4*)row)[3];
            float mx = fmaxf(fmaxf(fmaxf(x0.x, x0.y), fmaxf(x0.z, x0.w)),
                             fmaxf(fmaxf(x1.x, x1.y), fmaxf(x1.z, x1.w)));
            mx = fmaxf(mx, fmaxf(fmaxf(fmaxf(x2.x, x2.y), fmaxf(x2.z, x2.w)),
                                 fmaxf(fmaxf(x3.x, x3.y), fmaxf(x3.z, x3.w))));
            mx = fmaxf(mx, __shfl_xor_sync(0xffffffffu, mx, 1));
            mx = fmaxf(mx, __shfl_xor_sync(0xffffffffu, mx, 2));
            float mo = sM[r];
            float mn = fmaxf(mo, mx);
            x0.x = __expf(x0.x - mn); x0.y = __expf(x0.y - mn);
            x0.z = __expf(x0.z - mn); x0.w = __expf(x0.w - mn);
            x1.x = __expf(x1.x - mn); x1.y = __expf(x1.y - mn);
            x1.z = __expf(x1.z - mn); x1.w = __expf(x1.w - mn);
            x2.x = __expf(x2.x - mn); x2.y = __expf(x2.y - mn);
            x2.z = __expf(x2.z - mn); x2.w = __expf(x2.w - mn);
            x3.x = __expf(x3.x - mn); x3.y = __expf(x3.y - mn);
            x3.z = __expf(x3.z - mn); x3.w = __expf(x3.w - mn);
            float sum = (x0.x + x0.y + x0.z + x0.w) + (x1.x + x1.y + x1.z + x1.w)
                      + (x2.x + x2.y + x2.z + x2.w) + (x3.x + x3.y + x3.z + x3.w);
            sum += __shfl_xor_sync(0xffffffffu, sum, 1);
            sum += __shfl_xor_sync(0xffffffffu, sum, 2);
            ((float4*)row)[0] = x0; ((float4*)row)[1] = x1;
            ((float4*)row)[2] = x2; ((float4*)row)[3] = x3;
            if (seg == 0) {
                float fac = __expf(mo - mn);
                sM[r] = mn;
                sL[r] = sL[r] * fac + sum;
                sFac[r] = fac;
            }
        }
        __syncthreads();

        // O rescale, then O += P @ V  (64x64x64)
        #pragma unroll
        for (int mi = 0; mi < 2; mi++) {
            float f0 = sFac[wm + mi * 16 + tr];
            float f1 = sFac[wm + mi * 16 + tr + 8];
            #pragma unroll
            for (int ni = 0; ni < 2; ni++) {
                o[mi][ni][0] *= f0; o[mi][ni][1] *= f0;
                o[mi][ni][2] *= f1; o[mi][ni][3] *= f1;
            }
        }
        #pragma unroll
        for (int ks = 0; ks < 8; ks++) {
            const int kb = ks * 8;
            uint32_t af[2][4], bf[2][2];
            #pragma unroll
            for (int mi = 0; mi < 2; mi++) {
                int r = wm + mi * 16 + tr;
                af[mi][0] = to_tf32(sS[r * AS + kb + tc]);
                af[mi][1] = to_tf32(sS[(r + 8) * AS + kb + tc]);
                af[mi][2] = to_tf32(sS[r * AS + kb + tc + 4]);
                af[mi][3] = to_tf32(sS[(r + 8) * AS + kb + tc + 4]);
            }
            #pragma unroll
            for (int ni = 0; ni < 2; ni++) {
                int c = wn + ni * 8 + tr;
                bf[ni][0] = sV[(kb + tc) * VS + c];
                bf[ni][1] = sV[(kb + tc + 4) * VS + c];
            }
            #pragma unroll
            for (int mi = 0; mi < 2; mi++)
                #pragma unroll
                for (int ni = 0; ni < 2; ni++)
                    mma_tf32(o[mi][ni], af[mi], bf[ni], o[mi][ni]);
        }
    }

    // Normalize and store feats in [B, N, H]
    const int b = bh >> 4;
    const int h = bh & 15;
    #pragma unroll
    for (int mi = 0; mi < 2; mi++) {
        int r = wm + mi * 16 + tr;
        float inv0 = 1.0f / sL[r];
        float inv1 = 1.0f / sL[r + 8];
        int nrow = qt * 64 + r;
        #pragma unroll
        for (int ni = 0; ni < 2; ni++) {
            int c = h * HS_ + wn + ni * 8 + 2 * tc;
            *(float2*)&g_feats[((size_t)b * N_ + nrow) * H_ + c] =
                make_float2(o[mi][ni][0] * inv0, o[mi][ni][1] * inv0);
            *(float2*)&g_feats[((size_t)b * N_ + nrow + 8) * H_ + c] =
                make_float2(o[mi][ni][2] * inv1, o[mi][ni][3] * inv1);
        }
    }
}

// ---------------------------------------------------------------------------
// Launch
// ---------------------------------------------------------------------------
extern "C" void kernel_launch(void* const* d_in, const int* in_sizes, int n_in,
                              void* d_out, int out_size)
{
    const float* x  = (const float*)d_in[0];
    const float* ab = (const float*)d_in[1];
    const float* Wq = (const float*)d_in[2];
    const float* bq = (const float*)d_in[3];
    const float* Wk = (const float*)d_in[4];
    const float* bk = (const float*)d_in[5];
    const float* Wv = (const float*)d_in[6];
    const float* bv = (const float*)d_in[7];
    const float* Wp = (const float*)d_in[8];
    const float* bp = (const float*)d_in[9];
    float* out = (float*)d_out;

    float* gq; cudaGetSymbolAddress((void**)&gq, g_q);
    float* gk; cudaGetSymbolAddress((void**)&gk, g_k);
    float* gv; cudaGetSymbolAddress((void**)&gv, g_v);
    float* gf; cudaGetSymbolAddress((void**)&gf, g_feats);

    // 1) QKV projections (z selects Q/K/V)
    mm_mma<true><<<dim3(H_ / 128, M_ / 128, 3), 256>>>(
        x, Wq, bq, gq, Wk, bk, gk, Wv, bv, gv);

    // 2) Fused flash attention on mma.sync
    cudaFuncSetAttribute(attn_mma, cudaFuncAttributeMaxDynamicSharedMemorySize,
                         ATTN_SMEM);
    attn_mma<<<dim3(N_ / 64, B_ * NH_), 256, ATTN_SMEM>>>(ab);

    // 3) Output projection
    mm_mma<false><<<dim3(H_ / 128, M_ / 128, 1), 256>>>(
        gf, Wp, bp, out, Wp, bp, out, Wp, bp, out);
}

// round 6
// speedup vs baseline: 2.7826x; 1.0508x over previous
#include <cuda_runtime.h>
#include <math.h>
#include <stdint.h>

// Problem constants
#define B_  4
#define N_  1024
#define H_  1024
#define NH_ 16
#define HS_ 64
#define M_  (B_*N_)          // 4096 total rows

// Scratch (no cudaMalloc allowed)
__device__ float g_q[B_*NH_*N_*HS_];
__device__ float g_k[B_*NH_*N_*HS_];
__device__ float g_v[B_*NH_*N_*HS_];
__device__ float g_feats[B_*N_*H_];

// ---------------------------------------------------------------------------
// tf32 / cp.async helpers (all legal at compute_100; tcgen05 is NOT)
// ---------------------------------------------------------------------------
__device__ __forceinline__ uint32_t to_tf32(float x) {
    uint32_t u;
    asm("cvt.rna.tf32.f32 %0, %1;" : "=r"(u) : "f"(x));
    return u;
}

__device__ __forceinline__ void mma_tf32(float d[4], const uint32_t a[4],
                                         const uint32_t b[2], const float c[4]) {
    asm volatile(
        "mma.sync.aligned.m16n8k8.row.col.f32.tf32.tf32.f32 "
        "{%0,%1,%2,%3}, {%4,%5,%6,%7}, {%8,%9}, {%10,%11,%12,%13};"
        : "=f"(d[0]), "=f"(d[1]), "=f"(d[2]), "=f"(d[3])
        : "r"(a[0]), "r"(a[1]), "r"(a[2]), "r"(a[3]),
          "r"(b[0]), "r"(b[1]),
          "f"(c[0]), "f"(c[1]), "f"(c[2]), "f"(c[3]));
}

__device__ __forceinline__ void cpa16(void* dst, const void* src) {
    uint32_t d = (uint32_t)__cvta_generic_to_shared(dst);
    asm volatile("cp.async.cg.shared.global [%0], [%1], 16;" :: "r"(d), "l"(src));
}
#define CPA_COMMIT() asm volatile("cp.async.commit_group;")
#define CPA_WAIT2()  asm volatile("cp.async.wait_group 2;")

// Fast exp on the FMA pipe (no MUFU). x <= 0 expected; handles -inf via clamp.
// exp(x) = 2^(x*log2e); degree-6 Taylor of 2^f on [0,1), rel err ~1.5e-5.
__device__ __forceinline__ float fast_exp(float x) {
    float t = fmaxf(x * 1.4426950408889634f, -126.0f);
    int   ei = __float2int_rd(t);
    float f  = t - (float)ei;
    float p = 1.5353541e-4f;
    p = fmaf(p, f, 1.3398059e-3f);
    p = fmaf(p, f, 9.6180398e-3f);
    p = fmaf(p, f, 5.5504109e-2f);
    p = fmaf(p, f, 2.4022651e-1f);
    p = fmaf(p, f, 6.9314718e-1f);
    p = fmaf(p, f, 1.0f);
    return p * __int_as_float((ei + 127) << 23);
}

// ---------------------------------------------------------------------------
// GEMM: out[M,N] = A[M,K] @ W[K,N] + bias  (M=4096, N=K=1024), tf32 mma.sync
// CTA tile 128x128, K-step 32, 4-stage cp.async pipeline (f32 in smem,
// cvt->tf32 at fragment load). 8 warps = 4(m) x 2(n); warp tile 32x64.
// sA: [m][k] stride 36 words; sB: [k][n] stride 136 words (conflict-free).
// ---------------------------------------------------------------------------
#define GSA 36
#define GSB 136
#define SA_W (128 * GSA)             // 4608 words
#define SB_W (32 * GSB)              // 4352 words
#define STG_W (SA_W + SB_W)          // 8960 words = 35840 B
#define MM_SMEM (4 * STG_W * 4)      // 143360 B

template<bool SCATTER>
__global__ void __launch_bounds__(256) mm_mma(
    const float* __restrict__ A,
    const float* __restrict__ Wq, const float* __restrict__ bq, float* __restrict__ oq,
    const float* __restrict__ Wk, const float* __restrict__ bk, float* __restrict__ ok,
    const float* __restrict__ Wv, const float* __restrict__ bv, float* __restrict__ ov)
{
    extern __shared__ float smw[];

    const float* W; const float* bias; float* out;
    if (blockIdx.z == 0)      { W = Wq; bias = bq; out = oq; }
    else if (blockIdx.z == 1) { W = Wk; bias = bk; out = ok; }
    else                      { W = Wv; bias = bv; out = ov; }

    const int m0 = blockIdx.y * 128;
    const int n0 = blockIdx.x * 128;
    const int tid  = threadIdx.x;
    const int lane = tid & 31;
    const int warp = tid >> 5;
    const int wm = (warp & 3) * 32;      // warp m-offset
    const int wn = (warp >> 2) * 64;     // warp n-offset
    const int tr = lane >> 2;            // 0..7
    const int tc = lane & 3;             // 0..3

    float acc[2][8][4] = {};

    // Issue one pipeline stage: 8 cp.async (16B each) per thread
    auto issue_stage = [&](int stage, int k0) {
        float* sA = smw + stage * STG_W;
        float* sB = sA + SA_W;
        #pragma unroll
        for (int i = 0; i < 4; i++) {
            int fi = tid + 256 * i;               // 1024 A float4s
            int r = fi >> 3, kg = fi & 7;
            cpa16(&sA[r * GSA + kg * 4], &A[(size_t)(m0 + r) * H_ + k0 + kg * 4]);
        }
        #pragma unroll
        for (int i = 0; i < 4; i++) {
            int fi = tid + 256 * i;               // 1024 B float4s
            int kk = fi >> 5, ng = fi & 31;
            cpa16(&sB[kk * GSB + ng * 4], &W[(size_t)(k0 + kk) * H_ + n0 + ng * 4]);
        }
        CPA_COMMIT();
    };

    issue_stage(0, 0);
    issue_stage(1, 32);
    issue_stage(2, 64);

    for (int it = 0; it < 32; it++) {
        CPA_WAIT2();          // stage it landed
        __syncthreads();      // all warps done with MMA(it-1); stage visible

        const float* sA = smw + (it & 3) * STG_W;
        const float* sB = sA + SA_W;

        #pragma unroll
        for (int ks = 0; ks < 4; ks++) {
            const int kb = ks * 8;
            uint32_t af[2][4], bf[8][2];
            #pragma unroll
            for (int mi = 0; mi < 2; mi++) {
                int r = wm + mi * 16 + tr;
                af[mi][0] = to_tf32(sA[r * GSA + kb + tc]);
                af[mi][1] = to_tf32(sA[(r + 8) * GSA + kb + tc]);
                af[mi][2] = to_tf32(sA[r * GSA + kb + tc + 4]);
                af[mi][3] = to_tf32(sA[(r + 8) * GSA + kb + tc + 4]);
            }
            #pragma unroll
            for (int ni = 0; ni < 8; ni++) {
                int c = wn + ni * 8 + tr;
                bf[ni][0] = to_tf32(sB[(kb + tc) * GSB + c]);
                bf[ni][1] = to_tf32(sB[(kb + tc + 4) * GSB + c]);
            }
            #pragma unroll
            for (int mi = 0; mi < 2; mi++)
                #pragma unroll
                for (int ni = 0; ni < 8; ni++)
                    mma_tf32(acc[mi][ni], af[mi], bf[ni], acc[mi][ni]);
        }

        if (it + 3 < 32)
            issue_stage((it + 3) & 3, (it + 3) * 32);   // overwrites stage it-1 (safe: sync above)
    }

    // Epilogue: c0/c1 at (row, 2*tc), c2/c3 at (row+8, 2*tc)
    #pragma unroll
    for (int mi = 0; mi < 2; mi++) {
        int r = m0 + wm + mi * 16 + tr;
        #pragma unroll
        for (int ni = 0; ni < 8; ni++) {
            int c = n0 + wn + ni * 8 + 2 * tc;
            float2 bb = *(const float2*)&bias[c];
            float2 v0 = make_float2(acc[mi][ni][0] + bb.x, acc[mi][ni][1] + bb.y);
            float2 v1 = make_float2(acc[mi][ni][2] + bb.x, acc[mi][ni][3] + bb.y);
            if (SCATTER) {
                int b = r >> 10, nr = r & 1023;
                int h = c >> 6,  d  = c & 63;
                *(float2*)&out[(((size_t)b * NH_ + h) * N_ + nr)     * HS_ + d] = v0;
                *(float2*)&out[(((size_t)b * NH_ + h) * N_ + nr + 8) * HS_ + d] = v1;
            } else {
                *(float2*)&out[(size_t)r * H_ + c]       = v0;
                *(float2*)&out[(size_t)(r + 8) * H_ + c] = v1;
            }
        }
    }
}

// ---------------------------------------------------------------------------
// Fused flash attention with tf32 mma.sync + FMA-pipe exp + bias prefetch.
// Per CTA: one (b,h), one 64-row Q tile. 8 warps: 2(m) x 4(n), warp tile 32x16.
// ---------------------------------------------------------------------------
#define AS 68
#define VS 72
#define ATTN_SMEM ((64*AS*3 + 64*VS + 3*64) * 4)   // 71424 B

__global__ void __launch_bounds__(256) attn_mma(const float* __restrict__ bias4)
{
    extern __shared__ char smraw[];
    uint32_t* sQ = (uint32_t*)smraw;            // 64*68 words
    uint32_t* sK = sQ + 64 * AS;
    uint32_t* sV = sK + 64 * AS;                // 64*72 words
    float*    sS = (float*)(sV + 64 * VS);      // 64*68 words
    float*    sM   = sS + 64 * AS;
    float*    sL   = sM + 64;
    float*    sFac = sL + 64;

    const int bh = blockIdx.y;   // 0..63
    const int qt = blockIdx.x;   // 0..15
    const int tid  = threadIdx.x;
    const int lane = tid & 31;
    const int warp = tid >> 5;
    const int wm = (warp & 1) * 32;   // 2 warps along m
    const int wn = (warp >> 1) * 16;  // 4 warps along n
    const int tr = lane >> 2;
    const int tc = lane & 3;

    const float* qp = g_q + ((size_t)bh * N_ + qt * 64) * HS_;
    const float* kp = g_k + (size_t)bh * N_ * HS_;
    const float* vp = g_v + (size_t)bh * N_ * HS_;
    const float* bp = bias4 + (size_t)bh * N_ * N_ + (size_t)qt * 64 * N_;

    // Load Q tile (pre-scaled by 1/sqrt(HS), tf32)
    #pragma unroll
    for (int i = 0; i < 4; i++) {
        int fi = tid + 256 * i;           // 1024 float4s
        int r = fi >> 4, dq = fi & 15;
        float4 v = *(const float4*)&qp[(size_t)r * HS_ + dq * 4];
        uint4 u = make_uint4(to_tf32(v.x * 0.125f), to_tf32(v.y * 0.125f),
                             to_tf32(v.z * 0.125f), to_tf32(v.w * 0.125f));
        *(uint4*)&sQ[r * AS + dq * 4] = u;
    }
    { int r = tid >> 2; sM[r] = -INFINITY; sL[r] = 0.0f; sFac[r] = 0.0f; }

    float o[2][2][4] = {};

    for (int j = 0; j < 16; j++) {
        __syncthreads();   // prior iteration's MMA reads of sK/sV/sS done

        // Load K, V tiles (tf32 bits)
        #pragma unroll
        for (int i = 0; i < 4; i++) {
            int fi = tid + 256 * i;
            int r = fi >> 4, dq = fi & 15;
            float4 kv = *(const float4*)&kp[(size_t)(j * 64 + r) * HS_ + dq * 4];
            *(uint4*)&sK[r * AS + dq * 4] =
                make_uint4(to_tf32(kv.x), to_tf32(kv.y), to_tf32(kv.z), to_tf32(kv.w));
            float4 vv = *(const float4*)&vp[(size_t)(j * 64 + r) * HS_ + dq * 4];
            *(uint4*)&sV[r * VS + dq * 4] =
                make_uint4(to_tf32(vv.x), to_tf32(vv.y), to_tf32(vv.z), to_tf32(vv.w));
        }

        // Prefetch bias tile into registers (overlaps sync + QK^T MMAs)
        float2 pb[2][2][2];
        #pragma unroll
        for (int mi = 0; mi < 2; mi++) {
            int r = wm + mi * 16 + tr;
            #pragma unroll
            for (int ni = 0; ni < 2; ni++) {
                int c = wn + ni * 8 + 2 * tc;
                pb[mi][ni][0] = *(const float2*)&bp[(size_t)r * N_ + j * 64 + c];
                pb[mi][ni][1] = *(const float2*)&bp[(size_t)(r + 8) * N_ + j * 64 + c];
            }
        }
        __syncthreads();

        // S = Qs @ K^T   (64x64x64)
        float sacc[2][2][4] = {};
        #pragma unroll
        for (int ks = 0; ks < 8; ks++) {
            const int kb = ks * 8;
            uint32_t af[2][4], bf[2][2];
            #pragma unroll
            for (int mi = 0; mi < 2; mi++) {
                int r = wm + mi * 16 + tr;
                af[mi][0] = sQ[r * AS + kb + tc];
                af[mi][1] = sQ[(r + 8) * AS + kb + tc];
                af[mi][2] = sQ[r * AS + kb + tc + 4];
                af[mi][3] = sQ[(r + 8) * AS + kb + tc + 4];
            }
            #pragma unroll
            for (int ni = 0; ni < 2; ni++) {
                int c = wn + ni * 8 + tr;
                bf[ni][0] = sK[c * AS + kb + tc];
                bf[ni][1] = sK[c * AS + kb + tc + 4];
            }
            #pragma unroll
            for (int mi = 0; mi < 2; mi++)
                #pragma unroll
                for (int ni = 0; ni < 2; ni++)
                    mma_tf32(sacc[mi][ni], af[mi], bf[ni], sacc[mi][ni]);
        }

        // S + bias -> sS (fp32)
        #pragma unroll
        for (int mi = 0; mi < 2; mi++) {
            int r = wm + mi * 16 + tr;
            #pragma unroll
            for (int ni = 0; ni < 2; ni++) {
                int c = wn + ni * 8 + 2 * tc;
                *(float2*)&sS[r * AS + c] =
                    make_float2(sacc[mi][ni][0] + pb[mi][ni][0].x,
                                sacc[mi][ni][1] + pb[mi][ni][0].y);
                *(float2*)&sS[(r + 8) * AS + c] =
                    make_float2(sacc[mi][ni][2] + pb[mi][ni][1].x,
                                sacc[mi][ni][3] + pb[mi][ni][1].y);
            }
        }
        __syncthreads();

        // Online softmax: 4 lanes per row, 16 cols each; exp on FMA pipe
        {
            int r = tid >> 2, seg = tid & 3;
            float* row = &sS[r * AS + seg * 16];
            float4 x0 = ((float4*)row)[0], x1 = ((float4*)row)[1];
            float4 x2 = ((float4*)row)[2], x3 = ((float4*)row)[3];
            float mx = fmaxf(fmaxf(fmaxf(x0.x, x0.y), fmaxf(x0.z, x0.w)),
                             fmaxf(fmaxf(x1.x, x1.y), fmaxf(x1.z, x1.w)));
            mx = fmaxf(mx, fmaxf(fmaxf(fmaxf(x2.x, x2.y), fmaxf(x2.z, x2.w)),
                                 fmaxf(fmaxf(x3.x, x3.y), fmaxf(x3.z, x3.w))));
            mx = fmaxf(mx, __shfl_xor_sync(0xffffffffu, mx, 1));
            mx = fmaxf(mx, __shfl_xor_sync(0xffffffffu, mx, 2));
            float mo = sM[r];
            float mn = fmaxf(mo, mx);
            x0.x = fast_exp(x0.x - mn); x0.y = fast_exp(x0.y - mn);
            x0.z = fast_exp(x0.z - mn); x0.w = fast_exp(x0.w - mn);
            x1.x = fast_exp(x1.x - mn); x1.y = fast_exp(x1.y - mn);
            x1.z = fast_exp(x1.z - mn); x1.w = fast_exp(x1.w - mn);
            x2.x = fast_exp(x2.x - mn); x2.y = fast_exp(x2.y - mn);
            x2.z = fast_exp(x2.z - mn); x2.w = fast_exp(x2.w - mn);
            x3.x = fast_exp(x3.x - mn); x3.y = fast_exp(x3.y - mn);
            x3.z = fast_exp(x3.z - mn); x3.w = fast_exp(x3.w - mn);
            float sum = (x0.x + x0.y + x0.z + x0.w) + (x1.x + x1.y + x1.z + x1.w)
                      + (x2.x + x2.y + x2.z + x2.w) + (x3.x + x3.y + x3.z + x3.w);
            sum += __shfl_xor_sync(0xffffffffu, sum, 1);
            sum += __shfl_xor_sync(0xffffffffu, sum, 2);
            ((float4*)row)[0] = x0; ((float4*)row)[1] = x1;
            ((float4*)row)[2] = x2; ((float4*)row)[3] = x3;
            if (seg == 0) {
                float fac = fast_exp(mo - mn);
                sM[r] = mn;
                sL[r] = sL[r] * fac + sum;
                sFac[r] = fac;
            }
        }
        __syncthreads();

        // O rescale, then O += P @ V  (64x64x64)
        #pragma unroll
        for (int mi = 0; mi < 2; mi++) {
            float f0 = sFac[wm + mi * 16 + tr];
            float f1 = sFac[wm + mi * 16 + tr + 8];
            #pragma unroll
            for (int ni = 0; ni < 2; ni++) {
                o[mi][ni][0] *= f0; o[mi][ni][1] *= f0;
                o[mi][ni][2] *= f1; o[mi][ni][3] *= f1;
            }
        }
        #pragma unroll
        for (int ks = 0; ks < 8; ks++) {
            const int kb = ks * 8;
            uint32_t af[2][4], bf[2][2];
            #pragma unroll
            for (int mi = 0; mi < 2; mi++) {
                int r = wm + mi * 16 + tr;
                af[mi][0] = to_tf32(sS[r * AS + kb + tc]);
                af[mi][1] = to_tf32(sS[(r + 8) * AS + kb + tc]);
                af[mi][2] = to_tf32(sS[r * AS + kb + tc + 4]);
                af[mi][3] = to_tf32(sS[(r + 8) * AS + kb + tc + 4]);
            }
            #pragma unroll
            for (int ni = 0; ni < 2; ni++) {
                int c = wn + ni * 8 + tr;
                bf[ni][0] = sV[(kb + tc) * VS + c];
                bf[ni][1] = sV[(kb + tc + 4) * VS + c];
            }
            #pragma unroll
            for (int mi = 0; mi < 2; mi++)
                #pragma unroll
                for (int ni = 0; ni < 2; ni++)
                    mma_tf32(o[mi][ni], af[mi], bf[ni], o[mi][ni]);
        }
    }

    // Normalize and store feats in [B, N, H]
    const int b = bh >> 4;
    const int h = bh & 15;
    #pragma unroll
    for (int mi = 0; mi < 2; mi++) {
        int r = wm + mi * 16 + tr;
        float inv0 = 1.0f / sL[r];
        float inv1 = 1.0f / sL[r + 8];
        int nrow = qt * 64 + r;
        #pragma unroll
        for (int ni = 0; ni < 2; ni++) {
            int c = h * HS_ + wn + ni * 8 + 2 * tc;
            *(float2*)&g_feats[((size_t)b * N_ + nrow) * H_ + c] =
                make_float2(o[mi][ni][0] * inv0, o[mi][ni][1] * inv0);
            *(float2*)&g_feats[((size_t)b * N_ + nrow + 8) * H_ + c] =
                make_float2(o[mi][ni][2] * inv1, o[mi][ni][3] * inv1);
        }
    }
}

// ---------------------------------------------------------------------------
// Launch
// ---------------------------------------------------------------------------
extern "C" void kernel_launch(void* const* d_in, const int* in_sizes, int n_in,
                              void* d_out, int out_size)
{
    const float* x  = (const float*)d_in[0];
    const float* ab = (const float*)d_in[1];
    const float* Wq = (const float*)d_in[2];
    const float* bq = (const float*)d_in[3];
    const float* Wk = (const float*)d_in[4];
    const float* bk = (const float*)d_in[5];
    const float* Wv = (const float*)d_in[6];
    const float* bv = (const float*)d_in[7];
    const float* Wp = (const float*)d_in[8];
    const float* bp = (const float*)d_in[9];
    float* out = (float*)d_out;

    float* gq; cudaGetSymbolAddress((void**)&gq, g_q);
    float* gk; cudaGetSymbolAddress((void**)&gk, g_k);
    float* gv; cudaGetSymbolAddress((void**)&gv, g_v);
    float* gf; cudaGetSymbolAddress((void**)&gf, g_feats);

    cudaFuncSetAttribute(mm_mma<true>,  cudaFuncAttributeMaxDynamicSharedMemorySize, MM_SMEM);
    cudaFuncSetAttribute(mm_mma<false>, cudaFuncAttributeMaxDynamicSharedMemorySize, MM_SMEM);

    // 1) QKV projections (z selects Q/K/V)
    mm_mma<true><<<dim3(H_ / 128, M_ / 128, 3), 256, MM_SMEM>>>(
        x, Wq, bq, gq, Wk, bk, gk, Wv, bv, gv);

    // 2) Fused flash attention
    cudaFuncSetAttribute(attn_mma, cudaFuncAttributeMaxDynamicSharedMemorySize,
                         ATTN_SMEM);
    attn_mma<<<dim3(N_ / 64, B_ * NH_), 256, ATTN_SMEM>>>(ab);

    // 3) Output projection
    mm_mma<false><<<dim3(H_ / 128, M_ / 128, 1), 256, MM_SMEM>>>(
        gf, Wp, bp, out, Wp, bp, out, Wp, bp, out);
}

// round 7
// speedup vs baseline: 2.8626x; 1.0287x over previous
#include <cuda_runtime.h>
#include <math.h>
#include <stdint.h>

// Problem constants
#define B_  4
#define N_  1024
#define H_  1024
#define NH_ 16
#define HS_ 64
#define M_  (B_*N_)          // 4096 total rows

// Scratch (no cudaMalloc allowed)
__device__ float g_q[B_*NH_*N_*HS_];
__device__ float g_k[B_*NH_*N_*HS_];
__device__ float g_v[B_*NH_*N_*HS_];
__device__ float g_feats[B_*N_*H_];

// ---------------------------------------------------------------------------
// tf32 / cp.async helpers (all legal at compute_100; tcgen05 is NOT)
// ---------------------------------------------------------------------------
__device__ __forceinline__ uint32_t to_tf32(float x) {
    uint32_t u;
    asm("cvt.rna.tf32.f32 %0, %1;" : "=r"(u) : "f"(x));
    return u;
}

__device__ __forceinline__ void mma_tf32(float d[4], const uint32_t a[4],
                                         const uint32_t b[2], const float c[4]) {
    asm volatile(
        "mma.sync.aligned.m16n8k8.row.col.f32.tf32.tf32.f32 "
        "{%0,%1,%2,%3}, {%4,%5,%6,%7}, {%8,%9}, {%10,%11,%12,%13};"
        : "=f"(d[0]), "=f"(d[1]), "=f"(d[2]), "=f"(d[3])
        : "r"(a[0]), "r"(a[1]), "r"(a[2]), "r"(a[3]),
          "r"(b[0]), "r"(b[1]),
          "f"(c[0]), "f"(c[1]), "f"(c[2]), "f"(c[3]));
}

__device__ __forceinline__ void cpa16(void* dst, const void* src) {
    uint32_t d = (uint32_t)__cvta_generic_to_shared(dst);
    asm volatile("cp.async.cg.shared.global [%0], [%1], 16;" :: "r"(d), "l"(src));
}
#define CPA_COMMIT() asm volatile("cp.async.commit_group;")
#define CPA_WAIT1()  asm volatile("cp.async.wait_group 1;")

// Fast exp on the FMA pipe. x <= 0 expected; handles -inf via clamp.
__device__ __forceinline__ float fast_exp(float x) {
    float t = fmaxf(x * 1.4426950408889634f, -126.0f);
    int   ei = __float2int_rd(t);
    float f  = t - (float)ei;
    float p = 1.5353541e-4f;
    p = fmaf(p, f, 1.3398059e-3f);
    p = fmaf(p, f, 9.6180398e-3f);
    p = fmaf(p, f, 5.5504109e-2f);
    p = fmaf(p, f, 2.4022651e-1f);
    p = fmaf(p, f, 6.9314718e-1f);
    p = fmaf(p, f, 1.0f);
    return p * __int_as_float((ei + 127) << 23);
}

// ---------------------------------------------------------------------------
// GEMM: out[M,N] = A[M,K] @ W[K,N] + bias  (M=4096, N=K=1024), tf32 mma.sync
// CTA tile 128x128, K-step 32, 3-stage cp.async pipeline, 2 CTAs/SM.
// 8 warps = 4(m) x 2(n); warp tile 32x64.
// sA: [m][k] stride 36 words; sB: [k][n] stride 136 words (conflict-free).
// ---------------------------------------------------------------------------
#define GSA 36
#define GSB 136
#define SA_W (128 * GSA)             // 4608 words
#define SB_W (32 * GSB)              // 4352 words
#define STG_W (SA_W + SB_W)          // 8960 words = 35840 B
#define NSTAGE 3
#define MM_SMEM (NSTAGE * STG_W * 4) // 107520 B -> 2 CTAs/SM

template<bool SCATTER>
__global__ void __launch_bounds__(256, 2) mm_mma(
    const float* __restrict__ A,
    const float* __restrict__ Wq, const float* __restrict__ bq, float* __restrict__ oq,
    const float* __restrict__ Wk, const float* __restrict__ bk, float* __restrict__ ok,
    const float* __restrict__ Wv, const float* __restrict__ bv, float* __restrict__ ov)
{
    extern __shared__ float smw[];

    const float* W; const float* bias; float* out;
    if (blockIdx.z == 0)      { W = Wq; bias = bq; out = oq; }
    else if (blockIdx.z == 1) { W = Wk; bias = bk; out = ok; }
    else                      { W = Wv; bias = bv; out = ov; }

    const int m0 = blockIdx.y * 128;
    const int n0 = blockIdx.x * 128;
    const int tid  = threadIdx.x;
    const int lane = tid & 31;
    const int warp = tid >> 5;
    const int wm = (warp & 3) * 32;      // warp m-offset
    const int wn = (warp >> 2) * 64;     // warp n-offset
    const int tr = lane >> 2;            // 0..7
    const int tc = lane & 3;             // 0..3

    float acc[2][8][4] = {};

    // Issue one pipeline stage: 8 cp.async (16B each) per thread
    auto issue_stage = [&](int stage, int k0) {
        float* sA = smw + stage * STG_W;
        float* sB = sA + SA_W;
        #pragma unroll
        for (int i = 0; i < 4; i++) {
            int fi = tid + 256 * i;               // 1024 A float4s
            int r = fi >> 3, kg = fi & 7;
            cpa16(&sA[r * GSA + kg * 4], &A[(size_t)(m0 + r) * H_ + k0 + kg * 4]);
        }
        #pragma unroll
        for (int i = 0; i < 4; i++) {
            int fi = tid + 256 * i;               // 1024 B float4s
            int kk = fi >> 5, ng = fi & 31;
            cpa16(&sB[kk * GSB + ng * 4], &W[(size_t)(k0 + kk) * H_ + n0 + ng * 4]);
        }
        CPA_COMMIT();
    };

    issue_stage(0, 0);
    issue_stage(1, 32);

    int sidx = 0;
    for (int it = 0; it < 32; it++) {
        CPA_WAIT1();          // stage it landed (<=1 group outstanding)
        __syncthreads();      // all warps done with MMA(it-1); stage visible

        // Issue next stage FIRST so LDGs overlap the MMAs below.
        // Buffer (it+2)%3 == (it-1)%3: its consumers finished before the sync.
        if (it + 2 < 32) {
            int ns = sidx + 2; if (ns >= NSTAGE) ns -= NSTAGE;
            issue_stage(ns, (it + 2) * 32);
        }

        const float* sA = smw + sidx * STG_W;
        const float* sB = sA + SA_W;
        if (++sidx == NSTAGE) sidx = 0;

        #pragma unroll
        for (int ks = 0; ks < 4; ks++) {
            const int kb = ks * 8;
            uint32_t af[2][4], bf[8][2];
            #pragma unroll
            for (int mi = 0; mi < 2; mi++) {
                int r = wm + mi * 16 + tr;
                af[mi][0] = to_tf32(sA[r * GSA + kb + tc]);
                af[mi][1] = to_tf32(sA[(r + 8) * GSA + kb + tc]);
                af[mi][2] = to_tf32(sA[r * GSA + kb + tc + 4]);
                af[mi][3] = to_tf32(sA[(r + 8) * GSA + kb + tc + 4]);
            }
            #pragma unroll
            for (int ni = 0; ni < 8; ni++) {
                int c = wn + ni * 8 + tr;
                bf[ni][0] = to_tf32(sB[(kb + tc) * GSB + c]);
                bf[ni][1] = to_tf32(sB[(kb + tc + 4) * GSB + c]);
            }
            #pragma unroll
            for (int mi = 0; mi < 2; mi++)
                #pragma unroll
                for (int ni = 0; ni < 8; ni++)
                    mma_tf32(acc[mi][ni], af[mi], bf[ni], acc[mi][ni]);
        }
    }

    // Epilogue: c0/c1 at (row, 2*tc), c2/c3 at (row+8, 2*tc)
    #pragma unroll
    for (int mi = 0; mi < 2; mi++) {
        int r = m0 + wm + mi * 16 + tr;
        #pragma unroll
        for (int ni = 0; ni < 8; ni++) {
            int c = n0 + wn + ni * 8 + 2 * tc;
            float2 bb = *(const float2*)&bias[c];
            float2 v0 = make_float2(acc[mi][ni][0] + bb.x, acc[mi][ni][1] + bb.y);
            float2 v1 = make_float2(acc[mi][ni][2] + bb.x, acc[mi][ni][3] + bb.y);
            if (SCATTER) {
                int b = r >> 10, nr = r & 1023;
                int h = c >> 6,  d  = c & 63;
                *(float2*)&out[(((size_t)b * NH_ + h) * N_ + nr)     * HS_ + d] = v0;
                *(float2*)&out[(((size_t)b * NH_ + h) * N_ + nr + 8) * HS_ + d] = v1;
            } else {
                *(float2*)&out[(size_t)r * H_ + c]       = v0;
                *(float2*)&out[(size_t)(r + 8) * H_ + c] = v1;
            }
        }
    }
}

// ---------------------------------------------------------------------------
// Fused flash attention, tf32 mma.sync. K/V software-prefetched into registers
// during the previous iteration's PV phase (hides LDG latency).
// Per CTA: one (b,h), one 64-row Q tile. 8 warps: 2(m) x 4(n), warp tile 32x16.
// ---------------------------------------------------------------------------
#define AS 68
#define VS 72
#define ATTN_SMEM ((64*AS*3 + 64*VS + 3*64) * 4)   // 71424 B -> 2 CTAs/SM

__global__ void __launch_bounds__(256, 2) attn_mma(const float* __restrict__ bias4)
{
    extern __shared__ char smraw[];
    uint32_t* sQ = (uint32_t*)smraw;            // 64*68 words
    uint32_t* sK = sQ + 64 * AS;
    uint32_t* sV = sK + 64 * AS;                // 64*72 words
    float*    sS = (float*)(sV + 64 * VS);      // 64*68 words
    float*    sM   = sS + 64 * AS;
    float*    sL   = sM + 64;
    float*    sFac = sL + 64;

    const int bh = blockIdx.y;   // 0..63
    const int qt = blockIdx.x;   // 0..15
    const int tid  = threadIdx.x;
    const int lane = tid & 31;
    const int warp = tid >> 5;
    const int wm = (warp & 1) * 32;   // 2 warps along m
    const int wn = (warp >> 1) * 16;  // 4 warps along n
    const int tr = lane >> 2;
    const int tc = lane & 3;

    const float* qp = g_q + ((size_t)bh * N_ + qt * 64) * HS_;
    const float* kp = g_k + (size_t)bh * N_ * HS_;
    const float* vp = g_v + (size_t)bh * N_ * HS_;
    const float* bp = bias4 + (size_t)bh * N_ * N_ + (size_t)qt * 64 * N_;

    // Load Q tile (pre-scaled by 1/sqrt(HS), tf32)
    #pragma unroll
    for (int i = 0; i < 4; i++) {
        int fi = tid + 256 * i;           // 1024 float4s
        int r = fi >> 4, dq = fi & 15;
        float4 v = *(const float4*)&qp[(size_t)r * HS_ + dq * 4];
        uint4 u = make_uint4(to_tf32(v.x * 0.125f), to_tf32(v.y * 0.125f),
                             to_tf32(v.z * 0.125f), to_tf32(v.w * 0.125f));
        *(uint4*)&sQ[r * AS + dq * 4] = u;
    }
    { int r = tid >> 2; sM[r] = -INFINITY; sL[r] = 0.0f; sFac[r] = 0.0f; }

    // K/V register prefetch (4+4 float4 per thread)
    float4 rk[4], rv[4];
    auto load_kv = [&](int j) {
        #pragma unroll
        for (int i = 0; i < 4; i++) {
            int fi = tid + 256 * i;
            int r = fi >> 4, dq = fi & 15;
            rk[i] = *(const float4*)&kp[(size_t)(j * 64 + r) * HS_ + dq * 4];
            rv[i] = *(const float4*)&vp[(size_t)(j * 64 + r) * HS_ + dq * 4];
        }
    };
    load_kv(0);

    float o[2][2][4] = {};

    for (int j = 0; j < 16; j++) {
        __syncthreads();   // prior iteration's MMA reads of sK/sV/sS done

        // Commit prefetched K/V to smem (cvt to tf32 bits)
        #pragma unroll
        for (int i = 0; i < 4; i++) {
            int fi = tid + 256 * i;
            int r = fi >> 4, dq = fi & 15;
            *(uint4*)&sK[r * AS + dq * 4] =
                make_uint4(to_tf32(rk[i].x), to_tf32(rk[i].y), to_tf32(rk[i].z), to_tf32(rk[i].w));
            *(uint4*)&sV[r * VS + dq * 4] =
                make_uint4(to_tf32(rv[i].x), to_tf32(rv[i].y), to_tf32(rv[i].z), to_tf32(rv[i].w));
        }

        // Prefetch bias tile into registers (overlaps sync + QK^T MMAs)
        float2 pb[2][2][2];
        #pragma unroll
        for (int mi = 0; mi < 2; mi++) {
            int r = wm + mi * 16 + tr;
            #pragma unroll
            for (int ni = 0; ni < 2; ni++) {
                int c = wn + ni * 8 + 2 * tc;
                pb[mi][ni][0] = *(const float2*)&bp[(size_t)r * N_ + j * 64 + c];
                pb[mi][ni][1] = *(const float2*)&bp[(size_t)(r + 8) * N_ + j * 64 + c];
            }
        }
        __syncthreads();

        // S = Qs @ K^T   (64x64x64)
        float sacc[2][2][4] = {};
        #pragma unroll
        for (int ks = 0; ks < 8; ks++) {
            const int kb = ks * 8;
            uint32_t af[2][4], bf[2][2];
            #pragma unroll
            for (int mi = 0; mi < 2; mi++) {
                int r = wm + mi * 16 + tr;
                af[mi][0] = sQ[r * AS + kb + tc];
                af[mi][1] = sQ[(r + 8) * AS + kb + tc];
                af[mi][2] = sQ[r * AS + kb + tc + 4];
                af[mi][3] = sQ[(r + 8) * AS + kb + tc + 4];
            }
            #pragma unroll
            for (int ni = 0; ni < 2; ni++) {
                int c = wn + ni * 8 + tr;
                bf[ni][0] = sK[c * AS + kb + tc];
                bf[ni][1] = sK[c * AS + kb + tc + 4];
            }
            #pragma unroll
            for (int mi = 0; mi < 2; mi++)
                #pragma unroll
                for (int ni = 0; ni < 2; ni++)
                    mma_tf32(sacc[mi][ni], af[mi], bf[ni], sacc[mi][ni]);
        }

        // S + bias -> sS (fp32)
        #pragma unroll
        for (int mi = 0; mi < 2; mi++) {
            int r = wm + mi * 16 + tr;
            #pragma unroll
            for (int ni = 0; ni < 2; ni++) {
                int c = wn + ni * 8 + 2 * tc;
                *(float2*)&sS[r * AS + c] =
                    make_float2(sacc[mi][ni][0] + pb[mi][ni][0].x,
                                sacc[mi][ni][1] + pb[mi][ni][0].y);
                *(float2*)&sS[(r + 8) * AS + c] =
                    make_float2(sacc[mi][ni][2] + pb[mi][ni][1].x,
                                sacc[mi][ni][3] + pb[mi][ni][1].y);
            }
        }
        __syncthreads();

        // Online softmax: 4 lanes per row, 16 cols each; exp on FMA pipe
        {
            int r = tid >> 2, seg = tid & 3;
            float* row = &sS[r * AS + seg * 16];
            float4 x0 = ((float4*)row)[0], x1 = ((float4*)row)[1];
            float4 x2 = ((float4*)row)[2], x3 = ((float4*)row)[3];
            float mx = fmaxf(fmaxf(fmaxf(x0.x, x0.y), fmaxf(x0.z, x0.w)),
                             fmaxf(fmaxf(x1.x, x1.y), fmaxf(x1.z, x1.w)));
            mx = fmaxf(mx, fmaxf(fmaxf(fmaxf(x2.x, x2.y), fmaxf(x2.z, x2.w)),
                                 fmaxf(fmaxf(x3.x, x3.y), fmaxf(x3.z, x3.w))));
            mx = fmaxf(mx, __shfl_xor_sync(0xffffffffu, mx, 1));
            mx = fmaxf(mx, __shfl_xor_sync(0xffffffffu, mx, 2));
            float mo = sM[r];
            float mn = fmaxf(mo, mx);
            x0.x = fast_exp(x0.x - mn); x0.y = fast_exp(x0.y - mn);
            x0.z = fast_exp(x0.z - mn); x0.w = fast_exp(x0.w - mn);
            x1.x = fast_exp(x1.x - mn); x1.y = fast_exp(x1.y - mn);
            x1.z = fast_exp(x1.z - mn); x1.w = fast_exp(x1.w - mn);
            x2.x = fast_exp(x2.x - mn); x2.y = fast_exp(x2.y - mn);
            x2.z = fast_exp(x2.z - mn); x2.w = fast_exp(x2.w - mn);
            x3.x = fast_exp(x3.x - mn); x3.y = fast_exp(x3.y - mn);
            x3.z = fast_exp(x3.z - mn); x3.w = fast_exp(x3.w - mn);
            float sum = (x0.x + x0.y + x0.z + x0.w) + (x1.x + x1.y + x1.z + x1.w)
                      + (x2.x + x2.y + x2.z + x2.w) + (x3.x + x3.y + x3.z + x3.w);
            sum += __shfl_xor_sync(0xffffffffu, sum, 1);
            sum += __shfl_xor_sync(0xffffffffu, sum, 2);
            ((float4*)row)[0] = x0; ((float4*)row)[1] = x1;
            ((float4*)row)[2] = x2; ((float4*)row)[3] = x3;
            if (seg == 0) {
                float fac = fast_exp(mo - mn);
                sM[r] = mn;
                sL[r] = sL[r] * fac + sum;
                sFac[r] = fac;
            }
        }
        __syncthreads();

        // Prefetch next iteration's K/V (overlaps the PV MMAs below)
        if (j + 1 < 16) load_kv(j + 1);

        // O rescale, then O += P @ V  (64x64x64)
        #pragma unroll
        for (int mi = 0; mi < 2; mi++) {
            float f0 = sFac[wm + mi * 16 + tr];
            float f1 = sFac[wm + mi * 16 + tr + 8];
            #pragma unroll
            for (int ni = 0; ni < 2; ni++) {
                o[mi][ni][0] *= f0; o[mi][ni][1] *= f0;
                o[mi][ni][2] *= f1; o[mi][ni][3] *= f1;
            }
        }
        #pragma unroll
        for (int ks = 0; ks < 8; ks++) {
            const int kb = ks * 8;
            uint32_t af[2][4], bf[2][2];
            #pragma unroll
            for (int mi = 0; mi < 2; mi++) {
                int r = wm + mi * 16 + tr;
                af[mi][0] = to_tf32(sS[r * AS + kb + tc]);
                af[mi][1] = to_tf32(sS[(r + 8) * AS + kb + tc]);
                af[mi][2] = to_tf32(sS[r * AS + kb + tc + 4]);
                af[mi][3] = to_tf32(sS[(r + 8) * AS + kb + tc + 4]);
            }
            #pragma unroll
            for (int ni = 0; ni < 2; ni++) {
                int c = wn + ni * 8 + tr;
                bf[ni][0] = sV[(kb + tc) * VS + c];
                bf[ni][1] = sV[(kb + tc + 4) * VS + c];
            }
            #pragma unroll
            for (int mi = 0; mi < 2; mi++)
                #pragma unroll
                for (int ni = 0; ni < 2; ni++)
                    mma_tf32(o[mi][ni], af[mi], bf[ni], o[mi][ni]);
        }
    }

    // Normalize and store feats in [B, N, H]
    const int b = bh >> 4;
    const int h = bh & 15;
    #pragma unroll
    for (int mi = 0; mi < 2; mi++) {
        int r = wm + mi * 16 + tr;
        float inv0 = 1.0f / sL[r];
        float inv1 = 1.0f / sL[r + 8];
        int nrow = qt * 64 + r;
        #pragma unroll
        for (int ni = 0; ni < 2; ni++) {
            int c = h * HS_ + wn + ni * 8 + 2 * tc;
            *(float2*)&g_feats[((size_t)b * N_ + nrow) * H_ + c] =
                make_float2(o[mi][ni][0] * inv0, o[mi][ni][1] * inv0);
            *(float2*)&g_feats[((size_t)b * N_ + nrow + 8) * H_ + c] =
                make_float2(o[mi][ni][2] * inv1, o[mi][ni][3] * inv1);
        }
    }
}

// ---------------------------------------------------------------------------
// Launch
// ---------------------------------------------------------------------------
extern "C" void kernel_launch(void* const* d_in, const int* in_sizes, int n_in,
                              void* d_out, int out_size)
{
    const float* x  = (const float*)d_in[0];
    const float* ab = (const float*)d_in[1];
    const float* Wq = (const float*)d_in[2];
    const float* bq = (const float*)d_in[3];
    const float* Wk = (const float*)d_in[4];
    const float* bk = (const float*)d_in[5];
    const float* Wv = (const float*)d_in[6];
    const float* bv = (const float*)d_in[7];
    const float* Wp = (const float*)d_in[8];
    const float* bp = (const float*)d_in[9];
    float* out = (float*)d_out;

    float* gq; cudaGetSymbolAddress((void**)&gq, g_q);
    float* gk; cudaGetSymbolAddress((void**)&gk, g_k);
    float* gv; cudaGetSymbolAddress((void**)&gv, g_v);
    float* gf; cudaGetSymbolAddress((void**)&gf, g_feats);

    cudaFuncSetAttribute(mm_mma<true>,  cudaFuncAttributeMaxDynamicSharedMemorySize, MM_SMEM);
    cudaFuncSetAttribute(mm_mma<false>, cudaFuncAttributeMaxDynamicSharedMemorySize, MM_SMEM);

    // 1) QKV projections (z selects Q/K/V)
    mm_mma<true><<<dim3(H_ / 128, M_ / 128, 3), 256, MM_SMEM>>>(
        x, Wq, bq, gq, Wk, bk, gk, Wv, bv, gv);

    // 2) Fused flash attention
    cudaFuncSetAttribute(attn_mma, cudaFuncAttributeMaxDynamicSharedMemorySize,
                         ATTN_SMEM);
    attn_mma<<<dim3(N_ / 64, B_ * NH_), 256, ATTN_SMEM>>>(ab);

    // 3) Output projection
    mm_mma<false><<<dim3(H_ / 128, M_ / 128, 1), 256, MM_SMEM>>>(
        gf, Wp, bp, out, Wp, bp, out, Wp, bp, out);
}